// round 1
// baseline (speedup 1.0000x reference)
#include <cuda_runtime.h>
#include <cuda_bf16.h>
#include <math.h>

// ---------------- problem constants ----------------
#define BB   128
#define TT   256
#define TC   200
#define EE   256
#define HH   512
#define H4   2048
#define VV   50000
#define MAX_OOV 50
#define VEXT 50050

// ---------------- scratch (device globals; no allocation) ----------------
__device__ float g_emb[BB * EE];
__device__ float g_gates[BB * H4];
__device__ float g_dec[BB * HH];
__device__ float g_cdec[BB * HH];
__device__ float g_context[BB * HH];
__device__ float g_cctx[BB * HH];
__device__ float g_cscores[BB * TC];
__device__ float g_pgen[BB];

__device__ __forceinline__ float sigmoidf_(float x) {
    return 1.0f / (1.0f + __expf(-x));
}

// block reduce: op 0 = max, 1 = sum
__device__ __forceinline__ float block_reduce(float v, float* red, int op) {
    int lane = threadIdx.x & 31, warp = threadIdx.x >> 5;
    #pragma unroll
    for (int o = 16; o > 0; o >>= 1) {
        float u = __shfl_xor_sync(0xffffffffu, v, o);
        v = op ? (v + u) : fmaxf(v, u);
    }
    if (lane == 0) red[warp] = v;
    __syncthreads();
    int nw = (blockDim.x + 31) >> 5;
    if (warp == 0) {
        v = (lane < nw) ? red[lane] : (op ? 0.0f : -INFINITY);
        #pragma unroll
        for (int o = 16; o > 0; o >>= 1) {
            float u = __shfl_xor_sync(0xffffffffu, v, o);
            v = op ? (v + u) : fmaxf(v, u);
        }
        if (lane == 0) red[0] = v;
    }
    __syncthreads();
    float r = red[0];
    __syncthreads();
    return r;
}

// ---------------- embedding gather ----------------
__global__ void gather_emb_kernel(const int* __restrict__ input,
                                  const float* __restrict__ embedding) {
    int i = blockIdx.x * blockDim.x + threadIdx.x;  // B*E
    if (i >= BB * EE) return;
    int b = i / EE, e = i % EE;
    g_emb[i] = embedding[(size_t)input[b] * EE + e];
}

// ---------------- generic NT SGEMM: C[M,N] (+)= A[M,K] * W[N,K]^T + bias ----------------
template <int BM, int BN, int BK, int TM, int TN>
__global__ void sgemm_nt(const float* __restrict__ A, int lda,
                         const float* __restrict__ W, int ldw,
                         float* __restrict__ C, int ldc,
                         int M, int N, int K,
                         const float* __restrict__ bias,
                         const float* __restrict__ bias2,
                         int accum) {
    constexpr int THREADS = (BM / TM) * (BN / TN);  // 256 for both configs
    constexpr int PAD = 4;
    __shared__ float As[BK][BM + PAD];
    __shared__ float Bs[BK][BN + PAD];

    const int tid = threadIdx.x;
    const int n0 = blockIdx.x * BN;
    const int m0 = blockIdx.y * BM;
    const int tx = tid % (BN / TN);
    const int ty = tid / (BN / TN);

    float acc[TM][TN];
    #pragma unroll
    for (int i = 0; i < TM; i++)
        #pragma unroll
        for (int j = 0; j < TN; j++) acc[i][j] = 0.0f;

    constexpr int KQ = BK / 4;
    constexpr int LA = BM * BK / (4 * THREADS);
    constexpr int LB = BN * BK / (4 * THREADS);

    for (int kk = 0; kk < K; kk += BK) {
        #pragma unroll
        for (int r = 0; r < LA; r++) {
            int f = tid + r * THREADS;
            int row = f / KQ, kq = f % KQ;
            float4 v = *reinterpret_cast<const float4*>(
                &A[(size_t)(m0 + row) * lda + kk + kq * 4]);
            As[kq * 4 + 0][row] = v.x;
            As[kq * 4 + 1][row] = v.y;
            As[kq * 4 + 2][row] = v.z;
            As[kq * 4 + 3][row] = v.w;
        }
        #pragma unroll
        for (int r = 0; r < LB; r++) {
            int f = tid + r * THREADS;
            int row = f / KQ, kq = f % KQ;
            float4 v = make_float4(0.f, 0.f, 0.f, 0.f);
            if (n0 + row < N)
                v = *reinterpret_cast<const float4*>(
                    &W[(size_t)(n0 + row) * ldw + kk + kq * 4]);
            Bs[kq * 4 + 0][row] = v.x;
            Bs[kq * 4 + 1][row] = v.y;
            Bs[kq * 4 + 2][row] = v.z;
            Bs[kq * 4 + 3][row] = v.w;
        }
        __syncthreads();
        #pragma unroll
        for (int k = 0; k < BK; k++) {
            float a[TM], b[TN];
            #pragma unroll
            for (int i = 0; i < TM; i += 4) {
                float4 v = *reinterpret_cast<const float4*>(&As[k][ty * TM + i]);
                a[i + 0] = v.x; a[i + 1] = v.y; a[i + 2] = v.z; a[i + 3] = v.w;
            }
            #pragma unroll
            for (int j = 0; j < TN; j += 4) {
                float4 v = *reinterpret_cast<const float4*>(&Bs[k][tx * TN + j]);
                b[j + 0] = v.x; b[j + 1] = v.y; b[j + 2] = v.z; b[j + 3] = v.w;
            }
            #pragma unroll
            for (int i = 0; i < TM; i++)
                #pragma unroll
                for (int j = 0; j < TN; j++) acc[i][j] += a[i] * b[j];
        }
        __syncthreads();
    }

    #pragma unroll
    for (int i = 0; i < TM; i++) {
        int m = m0 + ty * TM + i;
        #pragma unroll
        for (int j = 0; j < TN; j++) {
            int n = n0 + tx * TN + j;
            if (n < N) {
                float v = acc[i][j];
                if (bias)  v += bias[n];
                if (bias2) v += bias2[n];
                if (accum) v += C[(size_t)m * ldc + n];
                C[(size_t)m * ldc + n] = v;
            }
        }
    }
}

// ---------------- LSTM pointwise ----------------
__global__ void lstm_kernel(const float* __restrict__ c0,
                            float* __restrict__ h1_out,
                            float* __restrict__ c1_out) {
    int i = blockIdx.x * blockDim.x + threadIdx.x;  // B*H
    if (i >= BB * HH) return;
    int b = i / HH, h = i % HH;
    const float* g = g_gates + (size_t)b * H4;
    float gi = g[h], gf = g[HH + h], gg = g[2 * HH + h], go = g[3 * HH + h];
    float c = sigmoidf_(gf) * c0[i] + sigmoidf_(gi) * tanhf(gg);
    float hh = sigmoidf_(go) * tanhf(c);
    c1_out[i] = c;
    h1_out[i] = hh;
}

// ---------------- fused attention: scores -> softmax -> context ----------------
__global__ void attn_kernel(const float* __restrict__ enc,   // [B][T][H]
                            const float* __restrict__ dec,   // [B][H]
                            float* __restrict__ ctx,         // [B][H]
                            float* __restrict__ scores_out,  // [B][T] or null
                            int T) {
    __shared__ float sdec[HH];
    __shared__ float sc[TT];
    __shared__ float red[32];
    int b = blockIdx.x;
    int tid = threadIdx.x;  // 256
    sdec[tid] = dec[b * HH + tid];
    sdec[tid + 256] = dec[b * HH + 256 + tid];
    __syncthreads();

    int warp = tid >> 5, lane = tid & 31;
    const float* eb = enc + (size_t)b * T * HH;

    // scores
    for (int t = warp; t < T; t += 8) {
        const float4* row = reinterpret_cast<const float4*>(eb + (size_t)t * HH);
        float s = 0.0f;
        #pragma unroll
        for (int q = 0; q < 4; q++) {
            int f4 = lane + 32 * q;
            float4 v = row[f4];
            s += v.x * sdec[f4 * 4 + 0] + v.y * sdec[f4 * 4 + 1] +
                 v.z * sdec[f4 * 4 + 2] + v.w * sdec[f4 * 4 + 3];
        }
        #pragma unroll
        for (int o = 16; o > 0; o >>= 1) s += __shfl_xor_sync(0xffffffffu, s, o);
        if (lane == 0) sc[t] = s;
    }
    __syncthreads();

    // softmax
    float m = -INFINITY;
    for (int t = tid; t < T; t += 256) m = fmaxf(m, sc[t]);
    m = block_reduce(m, red, 0);
    float ssum = 0.0f;
    for (int t = tid; t < T; t += 256) {
        float e = __expf(sc[t] - m);
        sc[t] = e;
        ssum += e;
    }
    ssum = block_reduce(ssum, red, 1);
    float inv = 1.0f / ssum;
    __syncthreads();

    if (scores_out) {
        for (int t = tid; t < T; t += 256)
            scores_out[(size_t)b * T + t] = sc[t] * inv;
    }

    // context
    for (int h = tid; h < HH; h += 256) {
        float a = 0.0f;
        for (int t = 0; t < T; t++) a += sc[t] * eb[(size_t)t * HH + h];
        ctx[(size_t)b * HH + h] = a * inv;
    }
}

// ---------------- p_gen ----------------
__global__ void pgen_kernel(const float* __restrict__ h1,
                            const float* __restrict__ gen_W,
                            const float* __restrict__ gen_b,
                            const float* __restrict__ sig_b,
                            const int* __restrict__ context_input) {
    __shared__ float red[32];
    int b = blockIdx.x;
    int tid = threadIdx.x;  // 256
    float s = 0.0f;
    for (int k = tid; k < HH; k += 256) s += g_context[b * HH + k] * gen_W[k];
    for (int k = tid; k < HH; k += 256) s += g_cctx[b * HH + k] * gen_W[HH + k];
    for (int k = tid; k < HH; k += 256) s += h1[b * HH + k] * gen_W[2 * HH + k];
    for (int k = tid; k < EE; k += 256) s += g_emb[b * EE + k] * gen_W[3 * HH + k];
    s = block_reduce(s, red, 1);

    float cnt = 0.0f;
    for (int t = tid; t < TC; t += 256)
        cnt += (context_input[(size_t)b * TC + t] > 0) ? 1.0f : 0.0f;
    cnt = block_reduce(cnt, red, 1);

    if (tid == 0) {
        float p = sigmoidf_(s + gen_b[0] + sig_b[0]);
        if (cnt == 0.0f) p = 1.0f;
        g_pgen[b] = p;
    }
}

// ---------------- softmax over logits (in d_out), scaled by p_gen ----------------
__global__ void softmax_kernel(float* __restrict__ out) {
    __shared__ float red[32];
    int b = blockIdx.x;
    int tid = threadIdx.x;  // 1024
    float* row = out + (size_t)b * VEXT;

    float m = -INFINITY;
    for (int v = tid; v < VV; v += 1024) m = fmaxf(m, row[v]);
    m = block_reduce(m, red, 0);

    float s = 0.0f;
    for (int v = tid; v < VV; v += 1024) s += __expf(row[v] - m);
    s = block_reduce(s, red, 1);

    float scale = g_pgen[b] / s;
    for (int v = tid; v < VV; v += 1024) row[v] = __expf(row[v] - m) * scale;
    for (int v = VV + tid; v < VEXT; v += 1024) row[v] = 0.0f;
}

// ---------------- copy distribution scatter ----------------
__global__ void scatter_kernel(const int* __restrict__ context_input,
                               float* __restrict__ out) {
    int i = blockIdx.x * blockDim.x + threadIdx.x;  // B*Tc
    if (i >= BB * TC) return;
    int b = i / TC;
    int idx = context_input[i];
    float w = (1.0f - g_pgen[b]) * g_cscores[i];
    atomicAdd(&out[(size_t)b * VEXT + idx], w);
}

// ---------------- final log(clip) ----------------
__global__ void log_kernel(float* __restrict__ out) {
    int i = blockIdx.x * blockDim.x + threadIdx.x;
    if (i >= BB * VEXT) return;
    float x = out[i];
    out[i] = logf(fmaxf(x, 1e-10f));
}

// ---------------- launcher ----------------
extern "C" void kernel_launch(void* const* d_in, const int* in_sizes, int n_in,
                              void* d_out, int out_size) {
    const int*   input    = (const int*)  d_in[0];
    const float* h0       = (const float*)d_in[1];
    const float* c0       = (const float*)d_in[2];
    const float* enc      = (const float*)d_in[3];
    const float* cenc     = (const float*)d_in[4];
    const int*   ctx_in   = (const int*)  d_in[5];
    const float* embedding= (const float*)d_in[6];
    const float* W_ih     = (const float*)d_in[7];
    const float* W_hh     = (const float*)d_in[8];
    const float* b_ih     = (const float*)d_in[9];
    const float* b_hh     = (const float*)d_in[10];
    const float* attn_W   = (const float*)d_in[11];
    const float* attn_b   = (const float*)d_in[12];
    const float* cattn_W  = (const float*)d_in[13];
    const float* cattn_b  = (const float*)d_in[14];
    const float* gen_W    = (const float*)d_in[15];
    const float* gen_b    = (const float*)d_in[16];
    const float* sig_b    = (const float*)d_in[17];
    const float* out_W    = (const float*)d_in[18];
    const float* out_b    = (const float*)d_in[19];

    float* out = (float*)d_out;
    float* logp   = out;
    float* h1_out = out + (size_t)BB * VEXT;
    float* c1_out = h1_out + (size_t)BB * HH;

    float* d_emb;     cudaGetSymbolAddress((void**)&d_emb,     g_emb);
    float* d_gates;   cudaGetSymbolAddress((void**)&d_gates,   g_gates);
    float* d_dec;     cudaGetSymbolAddress((void**)&d_dec,     g_dec);
    float* d_cdec;    cudaGetSymbolAddress((void**)&d_cdec,    g_cdec);
    float* d_context; cudaGetSymbolAddress((void**)&d_context, g_context);
    float* d_cctx;    cudaGetSymbolAddress((void**)&d_cctx,    g_cctx);
    float* d_cscores; cudaGetSymbolAddress((void**)&d_cscores, g_cscores);

    // 1) embedding gather
    gather_emb_kernel<<<(BB * EE + 255) / 256, 256>>>(input, embedding);

    // 2) gates = emb @ W_ih^T + b_ih + b_hh
    {
        dim3 grid(H4 / 64, BB / 64);
        sgemm_nt<64, 64, 16, 4, 4><<<grid, 256>>>(
            d_emb, EE, W_ih, EE, d_gates, H4, BB, H4, EE, b_ih, b_hh, 0);
    }
    // 3) gates += h0 @ W_hh^T
    {
        dim3 grid(H4 / 64, BB / 64);
        sgemm_nt<64, 64, 16, 4, 4><<<grid, 256>>>(
            h0, HH, W_hh, HH, d_gates, H4, BB, H4, HH, nullptr, nullptr, 1);
    }
    // 4) LSTM pointwise -> h1, c1 (directly into d_out tail)
    lstm_kernel<<<(BB * HH + 255) / 256, 256>>>(c0, h1_out, c1_out);

    // 5) dec = h1 @ attn_W^T + attn_b
    {
        dim3 grid(HH / 64, BB / 64);
        sgemm_nt<64, 64, 16, 4, 4><<<grid, 256>>>(
            h1_out, HH, attn_W, HH, d_dec, HH, BB, HH, HH, attn_b, nullptr, 0);
    }
    // 6) cdec = h1 @ cattn_W^T + cattn_b
    {
        dim3 grid(HH / 64, BB / 64);
        sgemm_nt<64, 64, 16, 4, 4><<<grid, 256>>>(
            h1_out, HH, cattn_W, HH, d_cdec, HH, BB, HH, HH, cattn_b, nullptr, 0);
    }
    // 7) encoder attention -> context
    attn_kernel<<<BB, 256>>>(enc, d_dec, d_context, nullptr, TT);
    // 8) context-encoder attention -> cctx (+ keep cscores)
    attn_kernel<<<BB, 256>>>(cenc, d_cdec, d_cctx, d_cscores, TC);

    // 9) p_gen
    pgen_kernel<<<BB, 256>>>(h1_out, gen_W, gen_b, sig_b, ctx_in);

    // 10) logits = h1 @ out_W^T + out_b  (into logp region, ldc = VEXT)
    {
        dim3 grid((VV + 127) / 128, BB / 128);
        sgemm_nt<128, 128, 16, 8, 8><<<grid, 256>>>(
            h1_out, HH, out_W, HH, logp, VEXT, BB, VV, HH, out_b, nullptr, 0);
    }

    // 11) softmax * p_gen in place (+ zero OOV tail)
    softmax_kernel<<<BB, 1024>>>(logp);

    // 12) copy scatter
    scatter_kernel<<<(BB * TC + 255) / 256, 256>>>(ctx_in, logp);

    // 13) log(clip)
    log_kernel<<<((size_t)BB * VEXT + 255) / 256, 256>>>(logp);
}

// round 3
// speedup vs baseline: 1.0430x; 1.0430x over previous
#include <cuda_runtime.h>
#include <cuda_bf16.h>
#include <mma.h>
#include <math.h>

using namespace nvcuda;

// ---------------- problem constants ----------------
#define BB   128
#define TT   256
#define TC   200
#define EE   256
#define HH   512
#define H4   2048
#define VV   50000
#define MAX_OOV 50
#define VEXT 50050
#define LPAD 50176   // padded logits row stride (multiple of 128)

// ---------------- scratch (device globals; no allocation) ----------------
__device__ float g_emb[BB * EE];
__device__ float g_gates1[BB * H4];
__device__ float g_gates2[BB * H4];
__device__ float g_dec[BB * HH];
__device__ float g_cdec[BB * HH];
__device__ float g_context[BB * HH];
__device__ float g_cctx[BB * HH];
__device__ float g_cscores[BB * TC];
__device__ float g_pgen[BB];
__device__ float g_logits[BB * LPAD];

__device__ __forceinline__ float sigmoidf_(float x) {
    return 1.0f / (1.0f + __expf(-x));
}

// block reduce: op 0 = max, 1 = sum
__device__ __forceinline__ float block_reduce(float v, float* red, int op) {
    int lane = threadIdx.x & 31, warp = threadIdx.x >> 5;
    #pragma unroll
    for (int o = 16; o > 0; o >>= 1) {
        float u = __shfl_xor_sync(0xffffffffu, v, o);
        v = op ? (v + u) : fmaxf(v, u);
    }
    if (lane == 0) red[warp] = v;
    __syncthreads();
    int nw = (blockDim.x + 31) >> 5;
    if (warp == 0) {
        v = (lane < nw) ? red[lane] : (op ? 0.0f : -INFINITY);
        #pragma unroll
        for (int o = 16; o > 0; o >>= 1) {
            float u = __shfl_xor_sync(0xffffffffu, v, o);
            v = op ? (v + u) : fmaxf(v, u);
        }
        if (lane == 0) red[0] = v;
    }
    __syncthreads();
    float r = red[0];
    __syncthreads();
    return r;
}

// ---------------- embedding gather ----------------
__global__ void gather_emb_kernel(const int* __restrict__ input,
                                  const float* __restrict__ embedding) {
    int i = blockIdx.x * blockDim.x + threadIdx.x;  // B*E
    if (i >= BB * EE) return;
    int b = i / EE, e = i % EE;
    g_emb[i] = embedding[(size_t)input[b] * EE + e];
}

// ---------------- tf32 tensor-core GEMM: C[128,N] = A[128,K] * W[N,K]^T ----------------
// M fixed at 128. 256 threads (8 warps, 2x4 warp grid). BN=128, BK=32.
// ldc must be a multiple of 4. Last N-tile may write garbage into padding
// columns n in [N, n0+128) — caller must guarantee ldc allocation covers it
// and downstream ignores those columns.
#define GBM 128
#define GBN 128
#define GBK 32
#define LDAS 40
#define LDWS 40

__global__ void __launch_bounds__(256)
wmma_gemm_nt(const float* __restrict__ A, int lda,
             const float* __restrict__ W, int ldw,
             float* __restrict__ C, int ldc,
             int N, int K) {
    __shared__ float As[GBM * LDAS];
    __shared__ float Ws[GBN * LDWS];

    const int tid = threadIdx.x;
    const int wid = tid >> 5;
    const int warp_m = wid >> 2;   // 0..1 -> 64-row slab
    const int warp_n = wid & 3;    // 0..3 -> 32-col slab
    const int n0 = blockIdx.x * GBN;

    wmma::fragment<wmma::accumulator, 16, 16, 8, float> c[4][2];
    #pragma unroll
    for (int i = 0; i < 4; i++)
        #pragma unroll
        for (int j = 0; j < 2; j++) wmma::fill_fragment(c[i][j], 0.0f);

    // 128 rows x 32 k = 4096 floats = 1024 float4 per tile; 256 threads -> 4 iters
    for (int kk = 0; kk < K; kk += GBK) {
        #pragma unroll
        for (int r = 0; r < 4; r++) {
            int f = tid + r * 256;          // 0..1023
            int row = f >> 3, kq = f & 7;   // row 0..127, kq 0..7
            float4 v = *reinterpret_cast<const float4*>(
                &A[(size_t)row * lda + kk + kq * 4]);
            float* dst = &As[row * LDAS + kq * 4];
            dst[0] = v.x; dst[1] = v.y; dst[2] = v.z; dst[3] = v.w;
        }
        #pragma unroll
        for (int r = 0; r < 4; r++) {
            int f = tid + r * 256;
            int row = f >> 3, kq = f & 7;
            float4 v = make_float4(0.f, 0.f, 0.f, 0.f);
            if (n0 + row < N)
                v = *reinterpret_cast<const float4*>(
                    &W[(size_t)(n0 + row) * ldw + kk + kq * 4]);
            float* dst = &Ws[row * LDWS + kq * 4];
            dst[0] = v.x; dst[1] = v.y; dst[2] = v.z; dst[3] = v.w;
        }
        __syncthreads();

        #pragma unroll
        for (int k8 = 0; k8 < GBK; k8 += 8) {
            wmma::fragment<wmma::matrix_a, 16, 16, 8, wmma::precision::tf32,
                           wmma::row_major> a[4];
            wmma::fragment<wmma::matrix_b, 16, 16, 8, wmma::precision::tf32,
                           wmma::col_major> b[2];
            #pragma unroll
            for (int mi = 0; mi < 4; mi++) {
                wmma::load_matrix_sync(a[mi],
                    &As[(warp_m * 64 + mi * 16) * LDAS + k8], LDAS);
                #pragma unroll
                for (int t = 0; t < a[mi].num_elements; t++)
                    a[mi].x[t] = wmma::__float_to_tf32(a[mi].x[t]);
            }
            #pragma unroll
            for (int ni = 0; ni < 2; ni++) {
                wmma::load_matrix_sync(b[ni],
                    &Ws[(warp_n * 32 + ni * 16) * LDWS + k8], LDWS);
                #pragma unroll
                for (int t = 0; t < b[ni].num_elements; t++)
                    b[ni].x[t] = wmma::__float_to_tf32(b[ni].x[t]);
            }
            #pragma unroll
            for (int mi = 0; mi < 4; mi++)
                #pragma unroll
                for (int ni = 0; ni < 2; ni++)
                    wmma::mma_sync(c[mi][ni], a[mi], b[ni], c[mi][ni]);
        }
        __syncthreads();
    }

    #pragma unroll
    for (int mi = 0; mi < 4; mi++)
        #pragma unroll
        for (int ni = 0; ni < 2; ni++)
            wmma::store_matrix_sync(
                &C[(size_t)(warp_m * 64 + mi * 16) * ldc + n0 + warp_n * 32 + ni * 16],
                c[mi][ni], ldc, wmma::mem_row_major);
}

// ---------------- LSTM pointwise (gates = g1 + g2 + b_ih + b_hh) ----------------
__global__ void lstm_kernel(const float* __restrict__ c0,
                            const float* __restrict__ b_ih,
                            const float* __restrict__ b_hh,
                            float* __restrict__ h1_out,
                            float* __restrict__ c1_out) {
    int i = blockIdx.x * blockDim.x + threadIdx.x;  // B*H
    if (i >= BB * HH) return;
    int b = i / HH, h = i % HH;
    const float* g1 = g_gates1 + (size_t)b * H4;
    const float* g2 = g_gates2 + (size_t)b * H4;
    float gi = g1[h]          + g2[h]          + b_ih[h]          + b_hh[h];
    float gf = g1[HH + h]     + g2[HH + h]     + b_ih[HH + h]     + b_hh[HH + h];
    float gg = g1[2 * HH + h] + g2[2 * HH + h] + b_ih[2 * HH + h] + b_hh[2 * HH + h];
    float go = g1[3 * HH + h] + g2[3 * HH + h] + b_ih[3 * HH + h] + b_hh[3 * HH + h];
    float c = sigmoidf_(gf) * c0[i] + sigmoidf_(gi) * tanhf(gg);
    float hh = sigmoidf_(go) * tanhf(c);
    c1_out[i] = c;
    h1_out[i] = hh;
}

// ---------------- fused attention: scores -> softmax -> context ----------------
__global__ void attn_kernel(const float* __restrict__ enc,   // [B][T][H]
                            const float* __restrict__ dec,   // [B][H] (pre-bias)
                            const float* __restrict__ bias,  // [H]
                            float* __restrict__ ctx,         // [B][H]
                            float* __restrict__ scores_out,  // [B][T] or null
                            int T) {
    __shared__ float sdec[HH];
    __shared__ float sc[TT];
    __shared__ float red[32];
    int b = blockIdx.x;
    int tid = threadIdx.x;  // 256
    sdec[tid]       = dec[b * HH + tid]       + bias[tid];
    sdec[tid + 256] = dec[b * HH + 256 + tid] + bias[256 + tid];
    __syncthreads();

    int warp = tid >> 5, lane = tid & 31;
    const float* eb = enc + (size_t)b * T * HH;

    // scores
    for (int t = warp; t < T; t += 8) {
        const float4* row = reinterpret_cast<const float4*>(eb + (size_t)t * HH);
        float s = 0.0f;
        #pragma unroll
        for (int q = 0; q < 4; q++) {
            int f4 = lane + 32 * q;
            float4 v = row[f4];
            s += v.x * sdec[f4 * 4 + 0] + v.y * sdec[f4 * 4 + 1] +
                 v.z * sdec[f4 * 4 + 2] + v.w * sdec[f4 * 4 + 3];
        }
        #pragma unroll
        for (int o = 16; o > 0; o >>= 1) s += __shfl_xor_sync(0xffffffffu, s, o);
        if (lane == 0) sc[t] = s;
    }
    __syncthreads();

    // softmax
    float m = -INFINITY;
    for (int t = tid; t < T; t += 256) m = fmaxf(m, sc[t]);
    m = block_reduce(m, red, 0);
    float ssum = 0.0f;
    for (int t = tid; t < T; t += 256) {
        float e = __expf(sc[t] - m);
        sc[t] = e;
        ssum += e;
    }
    ssum = block_reduce(ssum, red, 1);
    float inv = 1.0f / ssum;
    __syncthreads();

    if (scores_out) {
        for (int t = tid; t < T; t += 256)
            scores_out[(size_t)b * T + t] = sc[t] * inv;
    }

    // context: each thread owns h = tid and h = tid+256
    {
        float a0 = 0.0f, a1 = 0.0f;
        #pragma unroll 4
        for (int t = 0; t < T; t++) {
            float w = sc[t];
            a0 += w * eb[(size_t)t * HH + tid];
            a1 += w * eb[(size_t)t * HH + tid + 256];
        }
        ctx[(size_t)b * HH + tid]       = a0 * inv;
        ctx[(size_t)b * HH + tid + 256] = a1 * inv;
    }
}

// ---------------- p_gen ----------------
__global__ void pgen_kernel(const float* __restrict__ h1,
                            const float* __restrict__ gen_W,
                            const float* __restrict__ gen_b,
                            const float* __restrict__ sig_b,
                            const int* __restrict__ context_input) {
    __shared__ float red[32];
    int b = blockIdx.x;
    int tid = threadIdx.x;  // 256
    float s = 0.0f;
    for (int k = tid; k < HH; k += 256) s += g_context[b * HH + k] * gen_W[k];
    for (int k = tid; k < HH; k += 256) s += g_cctx[b * HH + k] * gen_W[HH + k];
    for (int k = tid; k < HH; k += 256) s += h1[b * HH + k] * gen_W[2 * HH + k];
    for (int k = tid; k < EE; k += 256) s += g_emb[b * EE + k] * gen_W[3 * HH + k];
    s = block_reduce(s, red, 1);

    float cnt = 0.0f;
    for (int t = tid; t < TC; t += 256)
        cnt += (context_input[(size_t)b * TC + t] > 0) ? 1.0f : 0.0f;
    cnt = block_reduce(cnt, red, 1);

    if (tid == 0) {
        float p = sigmoidf_(s + gen_b[0] + sig_b[0]);
        if (cnt == 0.0f) p = 1.0f;
        g_pgen[b] = p;
    }
}

// ---------------- softmax over logits (scratch) -> probs * p_gen into d_out ----------------
__global__ void softmax_kernel(const float* __restrict__ out_b,
                               float* __restrict__ out) {
    __shared__ float red[32];
    int b = blockIdx.x;
    int tid = threadIdx.x;  // 1024
    const float* lg = g_logits + (size_t)b * LPAD;
    float* row = out + (size_t)b * VEXT;

    float m = -INFINITY;
    for (int v = tid; v < VV; v += 1024) m = fmaxf(m, lg[v] + out_b[v]);
    m = block_reduce(m, red, 0);

    float s = 0.0f;
    for (int v = tid; v < VV; v += 1024) s += __expf(lg[v] + out_b[v] - m);
    s = block_reduce(s, red, 1);

    float scale = g_pgen[b] / s;
    for (int v = tid; v < VV; v += 1024) row[v] = __expf(lg[v] + out_b[v] - m) * scale;
    for (int v = VV + tid; v < VEXT; v += 1024) row[v] = 0.0f;
}

// ---------------- copy distribution scatter ----------------
__global__ void scatter_kernel(const int* __restrict__ context_input,
                               float* __restrict__ out) {
    int i = blockIdx.x * blockDim.x + threadIdx.x;  // B*Tc
    if (i >= BB * TC) return;
    int b = i / TC;
    int idx = context_input[i];
    float w = (1.0f - g_pgen[b]) * g_cscores[i];
    atomicAdd(&out[(size_t)b * VEXT + idx], w);
}

// ---------------- final log(clip) ----------------
__global__ void log_kernel(float* __restrict__ out) {
    int i = blockIdx.x * blockDim.x + threadIdx.x;
    if (i >= BB * VEXT) return;
    float x = out[i];
    out[i] = logf(fmaxf(x, 1e-10f));
}

// ---------------- launcher ----------------
extern "C" void kernel_launch(void* const* d_in, const int* in_sizes, int n_in,
                              void* d_out, int out_size) {
    const int*   input    = (const int*)  d_in[0];
    const float* h0       = (const float*)d_in[1];
    const float* c0       = (const float*)d_in[2];
    const float* enc      = (const float*)d_in[3];
    const float* cenc     = (const float*)d_in[4];
    const int*   ctx_in   = (const int*)  d_in[5];
    const float* embedding= (const float*)d_in[6];
    const float* W_ih     = (const float*)d_in[7];
    const float* W_hh     = (const float*)d_in[8];
    const float* b_ih     = (const float*)d_in[9];
    const float* b_hh     = (const float*)d_in[10];
    const float* attn_W   = (const float*)d_in[11];
    const float* attn_b   = (const float*)d_in[12];
    const float* cattn_W  = (const float*)d_in[13];
    const float* cattn_b  = (const float*)d_in[14];
    const float* gen_W    = (const float*)d_in[15];
    const float* gen_b    = (const float*)d_in[16];
    const float* sig_b    = (const float*)d_in[17];
    const float* out_W    = (const float*)d_in[18];
    const float* out_b    = (const float*)d_in[19];

    float* out = (float*)d_out;
    float* logp   = out;
    float* h1_out = out + (size_t)BB * VEXT;
    float* c1_out = h1_out + (size_t)BB * HH;

    float* d_emb;     cudaGetSymbolAddress((void**)&d_emb,     g_emb);
    float* d_gates1;  cudaGetSymbolAddress((void**)&d_gates1,  g_gates1);
    float* d_gates2;  cudaGetSymbolAddress((void**)&d_gates2,  g_gates2);
    float* d_dec;     cudaGetSymbolAddress((void**)&d_dec,     g_dec);
    float* d_cdec;    cudaGetSymbolAddress((void**)&d_cdec,    g_cdec);
    float* d_context; cudaGetSymbolAddress((void**)&d_context, g_context);
    float* d_cctx;    cudaGetSymbolAddress((void**)&d_cctx,    g_cctx);
    float* d_cscores; cudaGetSymbolAddress((void**)&d_cscores, g_cscores);
    float* d_logits;  cudaGetSymbolAddress((void**)&d_logits,  g_logits);

    // 1) embedding gather
    gather_emb_kernel<<<(BB * EE + 255) / 256, 256>>>(input, embedding);

    // 2) gates1 = emb @ W_ih^T        [N=2048, K=256]
    wmma_gemm_nt<<<H4 / GBN, 256>>>(d_emb, EE, W_ih, EE, d_gates1, H4, H4, EE);
    // 3) gates2 = h0 @ W_hh^T         [N=2048, K=512]
    wmma_gemm_nt<<<H4 / GBN, 256>>>(h0, HH, W_hh, HH, d_gates2, H4, H4, HH);
    // 4) LSTM pointwise -> h1, c1 (directly into d_out tail)
    lstm_kernel<<<(BB * HH + 255) / 256, 256>>>(c0, b_ih, b_hh, h1_out, c1_out);

    // 5) dec = h1 @ attn_W^T          [N=512, K=512]  (bias added in attn)
    wmma_gemm_nt<<<HH / GBN, 256>>>(h1_out, HH, attn_W, HH, d_dec, HH, HH, HH);
    // 6) cdec = h1 @ cattn_W^T
    wmma_gemm_nt<<<HH / GBN, 256>>>(h1_out, HH, cattn_W, HH, d_cdec, HH, HH, HH);

    // 7) encoder attention -> context
    attn_kernel<<<BB, 256>>>(enc, d_dec, attn_b, d_context, nullptr, TT);
    // 8) context-encoder attention -> cctx (+ keep cscores)
    attn_kernel<<<BB, 256>>>(cenc, d_cdec, cattn_b, d_cctx, d_cscores, TC);

    // 9) p_gen
    pgen_kernel<<<BB, 256>>>(h1_out, gen_W, gen_b, sig_b, ctx_in);

    // 10) logits = h1 @ out_W^T       [N=50000, K=512] -> padded scratch
    wmma_gemm_nt<<<(VV + GBN - 1) / GBN, 256>>>(
        h1_out, HH, out_W, HH, d_logits, LPAD, VV, HH);

    // 11) softmax * p_gen -> d_out (+ zero OOV tail, + out_b bias)
    softmax_kernel<<<BB, 1024>>>(out_b, logp);

    // 12) copy scatter
    scatter_kernel<<<(BB * TC + 255) / 256, 256>>>(ctx_in, logp);

    // 13) log(clip)
    log_kernel<<<((size_t)BB * VEXT + 255) / 256, 256>>>(logp);
}

// round 5
// speedup vs baseline: 1.5528x; 1.4888x over previous
#include <cuda_runtime.h>
#include <cuda_bf16.h>
#include <mma.h>
#include <math.h>
#include <cstdint>

using namespace nvcuda;

// ---------------- problem constants ----------------
#define BB   128
#define TT   256
#define TC   200
#define EE   256
#define HH   512
#define H4   2048
#define VV   50000
#define MAX_OOV 50
#define VEXT 50050
#define LPAD 50176   // padded logits row stride (multiple of 128)

#define ASTR 36      // smem row stride in floats (32 + 4 pad, 16B-aligned rows)

// ---------------- scratch (device globals; no allocation) ----------------
__device__ float g_gates[BB * H4];
__device__ float g_dec[BB * HH];
__device__ float g_cdec[BB * HH];
__device__ float g_context[BB * HH];
__device__ float g_cctx[BB * HH];
__device__ float g_cscores[BB * TC];
__device__ float g_pgen[BB];
__device__ float g_logits[BB * LPAD];

__device__ __forceinline__ float sigmoidf_(float x) {
    return 1.0f / (1.0f + __expf(-x));
}

// ---------------- cp.async helpers ----------------
__device__ __forceinline__ void cp_async16(uint32_t dst, const void* src) {
    asm volatile("cp.async.cg.shared.global [%0], [%1], 16;\n" :: "r"(dst), "l"(src));
}
__device__ __forceinline__ void cp_commit() {
    asm volatile("cp.async.commit_group;\n" ::);
}
template <int N>
__device__ __forceinline__ void cp_wait() {
    asm volatile("cp.async.wait_group %0;\n" :: "n"(N));
}

// block reduce: op 0 = max, 1 = sum
__device__ __forceinline__ float block_reduce(float v, float* red, int op) {
    int lane = threadIdx.x & 31, warp = threadIdx.x >> 5;
    #pragma unroll
    for (int o = 16; o > 0; o >>= 1) {
        float u = __shfl_xor_sync(0xffffffffu, v, o);
        v = op ? (v + u) : fmaxf(v, u);
    }
    if (lane == 0) red[warp] = v;
    __syncthreads();
    int nw = (blockDim.x + 31) >> 5;
    if (warp == 0) {
        v = (lane < nw) ? red[lane] : (op ? 0.0f : -INFINITY);
        #pragma unroll
        for (int o = 16; o > 0; o >>= 1) {
            float u = __shfl_xor_sync(0xffffffffu, v, o);
            v = op ? (v + u) : fmaxf(v, u);
        }
        if (lane == 0) red[0] = v;
    }
    __syncthreads();
    float r = red[0];
    __syncthreads();
    return r;
}

// ============================================================================
// tf32 tensor-core GEMM: C[128, N] = A[128, K] * W[N, K]^T
//   - M fixed 128, 128 threads (4 warps, 2x2 warp grid, 64 x BN/2 warp tiles)
//   - cp.async double-buffered smem, GBK = 32
//   - A K-concat: k < K1 -> A1 (optionally gathered by idx), else A2 at k-K1
//   - W K-concat: k < K1 -> W1 (ldw1), else W2 (ldw2) at k-K1
//   - W rows clamped to N-1 (pad columns produce duplicates; caller ignores)
// ============================================================================
template <int BN>
__global__ void __launch_bounds__(128, 2)
gemm_tc(const float* __restrict__ A1, int lda1,
        const float* __restrict__ A2, int lda2,
        const int* __restrict__ gather_idx,
        const float* __restrict__ W1, int ldw1,
        const float* __restrict__ W2, int ldw2,
        int K1,
        float* __restrict__ C, int ldc,
        int N, int K) {
    extern __shared__ float smem[];
    float* As = smem;                    // 2 stages x 128 x ASTR
    float* Ws = smem + 2 * 128 * ASTR;   // 2 stages x BN  x ASTR

    const int tid = threadIdx.x;
    const int wid = tid >> 5;
    const int warp_m = wid >> 1;         // 0..1
    const int warp_n = wid & 1;          // 0..1
    const int n0 = blockIdx.x * BN;
    constexpr int WN = BN / 2;
    constexpr int NI = WN / 16;          // 4 (BN=128) or 2 (BN=64)
    const int KT = K >> 5;               // k-tiles of 32

    const uint32_t as_base = (uint32_t)__cvta_generic_to_shared(As);
    const uint32_t ws_base = (uint32_t)__cvta_generic_to_shared(Ws);

    auto issue_stage = [&](int kt, int s) {
        const int kk = kt << 5;
        // A: 128 rows x 32 k = 1024 float4, 8 per thread
        #pragma unroll
        for (int r = 0; r < 8; r++) {
            int f = tid + r * 128;
            int row = f >> 3, kq = f & 7;
            int k = kk + kq * 4;
            const float* src;
            if (k < K1) {
                int arow = gather_idx ? gather_idx[row] : row;
                src = A1 + (size_t)arow * lda1 + k;
            } else {
                src = A2 + (size_t)row * lda2 + (k - K1);
            }
            cp_async16(as_base + (uint32_t)((s * 128 + row) * ASTR + kq * 4) * 4, src);
        }
        // W: BN rows x 32 k = BN*8 float4, BN/16 per thread
        #pragma unroll
        for (int r = 0; r < BN / 16; r++) {
            int f = tid + r * 128;
            int row = f >> 3, kq = f & 7;
            int k = kk + kq * 4;
            int nr = n0 + row;
            if (nr >= N) nr = N - 1;     // clamp (pad columns = dup of last row)
            const float* src = (k < K1)
                ? W1 + (size_t)nr * ldw1 + k
                : W2 + (size_t)nr * ldw2 + (k - K1);
            cp_async16(ws_base + (uint32_t)((s * BN + row) * ASTR + kq * 4) * 4, src);
        }
        cp_commit();
    };

    wmma::fragment<wmma::accumulator, 16, 16, 8, float> c[4][NI];
    #pragma unroll
    for (int i = 0; i < 4; i++)
        #pragma unroll
        for (int j = 0; j < NI; j++) wmma::fill_fragment(c[i][j], 0.0f);

    issue_stage(0, 0);

    for (int kt = 0; kt < KT; kt++) {
        if (kt + 1 < KT) {
            issue_stage(kt + 1, (kt + 1) & 1);
            cp_wait<1>();
        } else {
            cp_wait<0>();
        }
        __syncthreads();

        const int s = kt & 1;
        const float* as = As + (size_t)s * 128 * ASTR;
        const float* ws = Ws + (size_t)s * BN * ASTR;

        #pragma unroll
        for (int k8 = 0; k8 < 32; k8 += 8) {
            wmma::fragment<wmma::matrix_a, 16, 16, 8, wmma::precision::tf32,
                           wmma::row_major> a[4];
            wmma::fragment<wmma::matrix_b, 16, 16, 8, wmma::precision::tf32,
                           wmma::col_major> b[NI];
            #pragma unroll
            for (int mi = 0; mi < 4; mi++)
                wmma::load_matrix_sync(a[mi],
                    as + (warp_m * 64 + mi * 16) * ASTR + k8, ASTR);
            #pragma unroll
            for (int ni = 0; ni < NI; ni++)
                wmma::load_matrix_sync(b[ni],
                    ws + (warp_n * WN + ni * 16) * ASTR + k8, ASTR);
            #pragma unroll
            for (int mi = 0; mi < 4; mi++)
                #pragma unroll
                for (int ni = 0; ni < NI; ni++)
                    wmma::mma_sync(c[mi][ni], a[mi], b[ni], c[mi][ni]);
        }
        __syncthreads();
    }

    #pragma unroll
    for (int mi = 0; mi < 4; mi++)
        #pragma unroll
        for (int ni = 0; ni < NI; ni++)
            wmma::store_matrix_sync(
                &C[(size_t)(warp_m * 64 + mi * 16) * ldc + n0 + warp_n * WN + ni * 16],
                c[mi][ni], ldc, wmma::mem_row_major);
}

// ---------------- LSTM pointwise ----------------
__global__ void lstm_kernel(const float* __restrict__ c0,
                            const float* __restrict__ b_ih,
                            const float* __restrict__ b_hh,
                            float* __restrict__ h1_out,
                            float* __restrict__ c1_out) {
    int i = blockIdx.x * blockDim.x + threadIdx.x;  // B*H
    if (i >= BB * HH) return;
    int b = i / HH, h = i % HH;
    const float* g = g_gates + (size_t)b * H4;
    float gi = g[h]          + b_ih[h]          + b_hh[h];
    float gf = g[HH + h]     + b_ih[HH + h]     + b_hh[HH + h];
    float gg = g[2 * HH + h] + b_ih[2 * HH + h] + b_hh[2 * HH + h];
    float go = g[3 * HH + h] + b_ih[3 * HH + h] + b_hh[3 * HH + h];
    float c = sigmoidf_(gf) * c0[i] + sigmoidf_(gi) * tanhf(gg);
    float hh = sigmoidf_(go) * tanhf(c);
    c1_out[i] = c;
    h1_out[i] = hh;
}

// ---------------- fused attention ----------------
__global__ void attn_kernel(const float* __restrict__ enc,   // [B][T][H]
                            const float* __restrict__ dec,   // [B][H] (pre-bias)
                            const float* __restrict__ bias,  // [H]
                            float* __restrict__ ctx,         // [B][H]
                            float* __restrict__ scores_out,  // [B][T] or null
                            int T) {
    __shared__ float sdec[HH];
    __shared__ float sc[TT];
    __shared__ float red[32];
    int b = blockIdx.x;
    int tid = threadIdx.x;  // 256
    sdec[tid]       = dec[b * HH + tid]       + bias[tid];
    sdec[tid + 256] = dec[b * HH + 256 + tid] + bias[256 + tid];
    __syncthreads();

    int warp = tid >> 5, lane = tid & 31;
    const float* eb = enc + (size_t)b * T * HH;

    for (int t = warp; t < T; t += 8) {
        const float4* row = reinterpret_cast<const float4*>(eb + (size_t)t * HH);
        float s = 0.0f;
        #pragma unroll
        for (int q = 0; q < 4; q++) {
            int f4 = lane + 32 * q;
            float4 v = row[f4];
            s += v.x * sdec[f4 * 4 + 0] + v.y * sdec[f4 * 4 + 1] +
                 v.z * sdec[f4 * 4 + 2] + v.w * sdec[f4 * 4 + 3];
        }
        #pragma unroll
        for (int o = 16; o > 0; o >>= 1) s += __shfl_xor_sync(0xffffffffu, s, o);
        if (lane == 0) sc[t] = s;
    }
    __syncthreads();

    float m = -INFINITY;
    for (int t = tid; t < T; t += 256) m = fmaxf(m, sc[t]);
    m = block_reduce(m, red, 0);
    float ssum = 0.0f;
    for (int t = tid; t < T; t += 256) {
        float e = __expf(sc[t] - m);
        sc[t] = e;
        ssum += e;
    }
    ssum = block_reduce(ssum, red, 1);
    float inv = 1.0f / ssum;
    __syncthreads();

    if (scores_out) {
        for (int t = tid; t < T; t += 256)
            scores_out[(size_t)b * T + t] = sc[t] * inv;
    }

    {
        float a0 = 0.0f, a1 = 0.0f;
        #pragma unroll 4
        for (int t = 0; t < T; t++) {
            float w = sc[t];
            a0 += w * eb[(size_t)t * HH + tid];
            a1 += w * eb[(size_t)t * HH + tid + 256];
        }
        ctx[(size_t)b * HH + tid]       = a0 * inv;
        ctx[(size_t)b * HH + tid + 256] = a1 * inv;
    }
}

// ---------------- p_gen ----------------
__global__ void pgen_kernel(const float* __restrict__ h1,
                            const float* __restrict__ embedding,
                            const int* __restrict__ input,
                            const float* __restrict__ gen_W,
                            const float* __restrict__ gen_b,
                            const float* __restrict__ sig_b,
                            const int* __restrict__ context_input) {
    __shared__ float red[32];
    int b = blockIdx.x;
    int tid = threadIdx.x;  // 256
    float s = 0.0f;
    for (int k = tid; k < HH; k += 256) s += g_context[b * HH + k] * gen_W[k];
    for (int k = tid; k < HH; k += 256) s += g_cctx[b * HH + k] * gen_W[HH + k];
    for (int k = tid; k < HH; k += 256) s += h1[b * HH + k] * gen_W[2 * HH + k];
    {
        const float* emb = embedding + (size_t)input[b] * EE;
        for (int k = tid; k < EE; k += 256) s += emb[k] * gen_W[3 * HH + k];
    }
    s = block_reduce(s, red, 1);

    float cnt = 0.0f;
    for (int t = tid; t < TC; t += 256)
        cnt += (context_input[(size_t)b * TC + t] > 0) ? 1.0f : 0.0f;
    cnt = block_reduce(cnt, red, 1);

    if (tid == 0) {
        float p = sigmoidf_(s + gen_b[0] + sig_b[0]);
        if (cnt == 0.0f) p = 1.0f;
        g_pgen[b] = p;
    }
}

// ---------------- softmax (online max+sum, 2 reads) ----------------
__global__ void softmax_kernel(const float* __restrict__ out_b,
                               float* __restrict__ out) {
    __shared__ float red[32];
    int b = blockIdx.x;
    int tid = threadIdx.x;  // 1024
    const float* lg = g_logits + (size_t)b * LPAD;
    float* row = out + (size_t)b * VEXT;

    // pass 1: thread-local online (m, s)
    float m = -INFINITY, s = 0.0f;
    for (int v = tid; v < VV; v += 1024) {
        float x = lg[v] + out_b[v];
        if (x > m) {
            s = s * __expf(m - x) + 1.0f;
            m = x;
        } else {
            s += __expf(x - m);
        }
    }
    float M = block_reduce(m, red, 0);
    s = (m == -INFINITY) ? 0.0f : s * __expf(m - M);
    float S = block_reduce(s, red, 1);

    float scale = g_pgen[b] / S;
    for (int v = tid; v < VV; v += 1024)
        row[v] = __expf(lg[v] + out_b[v] - M) * scale;
    for (int v = VV + tid; v < VEXT; v += 1024) row[v] = 0.0f;
}

// ---------------- copy distribution scatter ----------------
__global__ void scatter_kernel(const int* __restrict__ context_input,
                               float* __restrict__ out) {
    int i = blockIdx.x * blockDim.x + threadIdx.x;  // B*Tc
    if (i >= BB * TC) return;
    int b = i / TC;
    int idx = context_input[i];
    float w = (1.0f - g_pgen[b]) * g_cscores[i];
    atomicAdd(&out[(size_t)b * VEXT + idx], w);
}

// ---------------- final log(clip), vectorized ----------------
__global__ void log_kernel(float* __restrict__ out) {
    const int n4 = (BB * VEXT) / 4;  // 6,406,400 / 4 — exact
    int i = blockIdx.x * blockDim.x + threadIdx.x;
    if (i >= n4) return;
    float4 v = reinterpret_cast<float4*>(out)[i];
    v.x = __logf(fmaxf(v.x, 1e-10f));
    v.y = __logf(fmaxf(v.y, 1e-10f));
    v.z = __logf(fmaxf(v.z, 1e-10f));
    v.w = __logf(fmaxf(v.w, 1e-10f));
    reinterpret_cast<float4*>(out)[i] = v;
}

// ---------------- launcher ----------------
extern "C" void kernel_launch(void* const* d_in, const int* in_sizes, int n_in,
                              void* d_out, int out_size) {
    const int*   input    = (const int*)  d_in[0];
    const float* h0       = (const float*)d_in[1];
    const float* c0       = (const float*)d_in[2];
    const float* enc      = (const float*)d_in[3];
    const float* cenc     = (const float*)d_in[4];
    const int*   ctx_in   = (const int*)  d_in[5];
    const float* embedding= (const float*)d_in[6];
    const float* W_ih     = (const float*)d_in[7];
    const float* W_hh     = (const float*)d_in[8];
    const float* b_ih     = (const float*)d_in[9];
    const float* b_hh     = (const float*)d_in[10];
    const float* attn_W   = (const float*)d_in[11];
    const float* attn_b   = (const float*)d_in[12];
    const float* cattn_W  = (const float*)d_in[13];
    const float* cattn_b  = (const float*)d_in[14];
    const float* gen_W    = (const float*)d_in[15];
    const float* gen_b    = (const float*)d_in[16];
    const float* sig_b    = (const float*)d_in[17];
    const float* out_W    = (const float*)d_in[18];
    const float* out_b    = (const float*)d_in[19];

    float* out = (float*)d_out;
    float* logp   = out;
    float* h1_out = out + (size_t)BB * VEXT;
    float* c1_out = h1_out + (size_t)BB * HH;

    float* d_gates;   cudaGetSymbolAddress((void**)&d_gates,   g_gates);
    float* d_dec;     cudaGetSymbolAddress((void**)&d_dec,     g_dec);
    float* d_cdec;    cudaGetSymbolAddress((void**)&d_cdec,    g_cdec);
    float* d_context; cudaGetSymbolAddress((void**)&d_context, g_context);
    float* d_cctx;    cudaGetSymbolAddress((void**)&d_cctx,    g_cctx);
    float* d_cscores; cudaGetSymbolAddress((void**)&d_cscores, g_cscores);
    float* d_logits;  cudaGetSymbolAddress((void**)&d_logits,  g_logits);

    const int SMEM128 = (2 * 128 * ASTR + 2 * 128 * ASTR) * 4;  // 73728
    const int SMEM64  = (2 * 128 * ASTR + 2 * 64  * ASTR) * 4;  // 55296
    cudaFuncSetAttribute(gemm_tc<128>,
        cudaFuncAttributeMaxDynamicSharedMemorySize, SMEM128);
    cudaFuncSetAttribute(gemm_tc<64>,
        cudaFuncAttributeMaxDynamicSharedMemorySize, SMEM64);

    // 1) gates = [emb | h0] @ [W_ih | W_hh]^T   (K=768, K1=256, emb gathered)
    gemm_tc<64><<<H4 / 64, 128, SMEM64>>>(
        embedding, EE, h0, HH, input,
        W_ih, EE, W_hh, HH, EE,
        d_gates, H4, H4, EE + HH);

    // 2) LSTM pointwise -> h1, c1 (into d_out tail)
    lstm_kernel<<<(BB * HH + 255) / 256, 256>>>(c0, b_ih, b_hh, h1_out, c1_out);

    // 3) dec = h1 @ attn_W^T
    gemm_tc<64><<<HH / 64, 128, SMEM64>>>(
        h1_out, HH, h1_out, HH, nullptr,
        attn_W, HH, attn_W, HH, HH,
        d_dec, HH, HH, HH);

    // 4) BIG: logits = h1 @ out_W^T  (N=50176 padded, rows clamped) [ncu slot]
    gemm_tc<128><<<LPAD / 128, 128, SMEM128>>>(
        h1_out, HH, h1_out, HH, nullptr,
        out_W, HH, out_W, HH, HH,
        d_logits, LPAD, VV, HH);

    // 5) cdec = h1 @ cattn_W^T
    gemm_tc<64><<<HH / 64, 128, SMEM64>>>(
        h1_out, HH, h1_out, HH, nullptr,
        cattn_W, HH, cattn_W, HH, HH,
        d_cdec, HH, HH, HH);

    // 6) encoder attention -> context
    attn_kernel<<<BB, 256>>>(enc, d_dec, attn_b, d_context, nullptr, TT);
    // 7) context-encoder attention -> cctx (+ cscores)
    attn_kernel<<<BB, 256>>>(cenc, d_cdec, cattn_b, d_cctx, d_cscores, TC);

    // 8) p_gen
    pgen_kernel<<<BB, 256>>>(h1_out, embedding, input, gen_W, gen_b, sig_b, ctx_in);

    // 9) softmax * p_gen -> d_out (+ out_b bias, zero OOV tail)
    softmax_kernel<<<BB, 1024>>>(out_b, logp);

    // 10) copy scatter
    scatter_kernel<<<(BB * TC + 255) / 256, 256>>>(ctx_in, logp);

    // 11) log(clip)
    log_kernel<<<((BB * VEXT) / 4 + 255) / 256, 256>>>(logp);
}